// round 11
// baseline (speedup 1.0000x reference)
#include <cuda_runtime.h>
#include <math.h>

// Problem constants (fixed shapes from reference setup_inputs)
#define NMAX 40000
#define EMAX 640000
#define HID  128
#define FIN  64
#define FOUT 64
#define STATS_BLOCKS 2048
#define STATS_BLOCKS_N 512
#define SCAN_BLK 256

// ---------------- device scratch (allocation-free: static globals) ----------------
__device__ float g_A[NMAX * HID];      // x @ W1a.T   [N,128]
__device__ float g_B[NMAX * HID];      // x @ W1b.T   [N,128]
__device__ float g_h1[NMAX * HID];     // h1 rows 0..N  (A[src]+B[dst])
__device__ float g_agg1[NMAX * HID];   // edge-aggregated h1
__device__ float g_wz[NMAX * FOUT];    // W2l @ r_j for j<N
__device__ float g_wa2[NMAX * FOUT];   // edge-aggregated wz
__device__ int   g_cnt[NMAX];
__device__ int   g_fill[NMAX];
__device__ int   g_rowptr[NMAX + 1];
__device__ int   g_bsum[(NMAX + SCAN_BLK - 1) / SCAN_BLK + 1];
__device__ int   g_eid[EMAX];
__device__ int   g_csrc[EMAX];
__device__ float g_cnorm[EMAX];
__device__ float g_dis[NMAX];
__device__ float g_invdeg[NMAX];
__device__ float g_part[(STATS_BLOCKS + STATS_BLOCKS_N) * 2 * HID];
__device__ float g_af[HID];
__device__ float g_cf[HID];
__device__ float g_W2l[FOUT * HID];    // Wl @ W2  [64,128]
__device__ float g_cvec[FOUT];         // Wl@b2 + bl

// ---------------- f32x2 helpers ----------------
__device__ __forceinline__ unsigned long long fma2(unsigned long long a,
                                                   unsigned long long b,
                                                   unsigned long long c) {
    unsigned long long d;
    asm("fma.rn.f32x2 %0, %1, %2, %3;" : "=l"(d) : "l"(a), "l"(b), "l"(c));
    return d;
}
__device__ __forceinline__ unsigned long long add2(unsigned long long a,
                                                   unsigned long long b) {
    unsigned long long d;
    asm("add.rn.f32x2 %0, %1, %2;" : "=l"(d) : "l"(a), "l"(b));
    return d;
}
__device__ __forceinline__ unsigned long long packf2(float lo, float hi) {
    return ((unsigned long long)__float_as_uint(hi) << 32) | __float_as_uint(lo);
}
__device__ __forceinline__ float f2lo(unsigned long long a) {
    return __uint_as_float((unsigned int)a);
}
__device__ __forceinline__ float f2hi(unsigned long long a) {
    return __uint_as_float((unsigned int)(a >> 32));
}

// ---------------- kernels ----------------

__global__ void k_zero(int Ncur) {
    int t = blockIdx.x * blockDim.x + threadIdx.x;
    if (t < Ncur) { g_cnt[t] = 0; g_fill[t] = 0; }
}

__global__ void k_count(const int* __restrict__ dst, int Ecur) {
    int e = blockIdx.x * blockDim.x + threadIdx.x;
    if (e < Ecur) atomicAdd(&g_cnt[dst[e]], 1);
}

// BN stats part E: rows i in [N, E) — pre = A[src]+B[dst]+b1.
// 8 rows per iteration; predication-free main loop + scalar tail.
// grid=2048 for occupancy (latency-bound; R10 profile showed occ=42% at 1024).
__global__ void __launch_bounds__(128) k_bnstatsE(const int* __restrict__ src,
                                                  const int* __restrict__ dst,
                                                  const float* __restrict__ b1,
                                                  int Ncur, int Ecur) {
    int f = threadIdx.x;
    float bb = b1[f];
    float s_ = 0.f, q_ = 0.f;
    int stride = gridDim.x * 8;
    int i = Ncur + blockIdx.x * 8;
    for (; i + 8 <= Ecur; i += stride) {
        int sn[8], dn[8];
#pragma unroll
        for (int k = 0; k < 8; k++) { sn[k] = src[i + k]; dn[k] = dst[i + k]; }
        float vA[8], vB[8];
#pragma unroll
        for (int k = 0; k < 8; k++) {
            vA[k] = g_A[sn[k] * HID + f];
            vB[k] = g_B[dn[k] * HID + f];
        }
#pragma unroll
        for (int k = 0; k < 8; k++) {
            float v = vA[k] + vB[k] + bb;
            s_ += v;
            q_ = fmaf(v, v, q_);
        }
    }
    for (; i < Ecur; i++) {
        float v = g_A[src[i] * HID + f] + g_B[dst[i] * HID + f] + bb;
        s_ += v;
        q_ = fmaf(v, v, q_);
    }
    g_part[blockIdx.x * (2 * HID) + f]       = s_;
    g_part[blockIdx.x * (2 * HID) + HID + f] = q_;
}

// BN stats part N: rows j in [0, N) — pre = invdeg*(A[src]+B[dst]) + agg1 + b1
__global__ void __launch_bounds__(128) k_bnstatsN(const int* __restrict__ src,
                                                  const int* __restrict__ dst,
                                                  const float* __restrict__ b1,
                                                  int Ncur) {
    int f = threadIdx.x;
    float bb = b1[f];
    float s_ = 0.f, q_ = 0.f;
    int stride = gridDim.x * 8;
    int j = blockIdx.x * 8;
    for (; j + 8 <= Ncur; j += stride) {
        int sn[8], dn[8];
#pragma unroll
        for (int k = 0; k < 8; k++) { sn[k] = src[j + k]; dn[k] = dst[j + k]; }
        float vA[8], vB[8], ag[8], idg[8];
#pragma unroll
        for (int k = 0; k < 8; k++) {
            vA[k]  = g_A[sn[k] * HID + f];
            vB[k]  = g_B[dn[k] * HID + f];
            ag[k]  = g_agg1[(j + k) * HID + f];
            idg[k] = g_invdeg[j + k];
        }
#pragma unroll
        for (int k = 0; k < 8; k++) {
            float v = idg[k] * (vA[k] + vB[k]) + ag[k] + bb;
            s_ += v;
            q_ = fmaf(v, v, q_);
        }
    }
    for (; j < Ncur; j++) {
        float v = g_invdeg[j] * (g_A[src[j] * HID + f] + g_B[dst[j] * HID + f])
                + g_agg1[j * HID + f] + bb;
        s_ += v;
        q_ = fmaf(v, v, q_);
    }
    size_t base = (size_t)(STATS_BLOCKS + blockIdx.x) * (2 * HID);
    g_part[base + f]       = s_;
    g_part[base + HID + f] = q_;
}

// scan pass 1: per-block exclusive scan + block totals; fused deg normalizers
__global__ void __launch_bounds__(SCAN_BLK) k_scan1(int Ncur) {
    __shared__ int sh[SCAN_BLK];
    int t = threadIdx.x;
    int idx = blockIdx.x * SCAN_BLK + t;
    int v = (idx < Ncur) ? g_cnt[idx] : 0;
    if (idx < Ncur) {
        float dg = (float)(v + 1);
        g_dis[idx]    = rsqrtf(dg);
        g_invdeg[idx] = 1.0f / dg;
    }
    sh[t] = v;
    __syncthreads();
#pragma unroll
    for (int off = 1; off < SCAN_BLK; off <<= 1) {
        int xv = (t >= off) ? sh[t - off] : 0;
        __syncthreads();
        sh[t] += xv;
        __syncthreads();
    }
    if (idx < Ncur) g_rowptr[idx] = sh[t] - v;
    if (t == SCAN_BLK - 1) g_bsum[blockIdx.x] = sh[t];
}

// scan pass 2: exclusive scan of block sums (nb <= SCAN_BLK)
__global__ void __launch_bounds__(SCAN_BLK) k_scan2(int nb) {
    __shared__ int sh[SCAN_BLK];
    int t = threadIdx.x;
    int v = (t < nb) ? g_bsum[t] : 0;
    sh[t] = v;
    __syncthreads();
#pragma unroll
    for (int off = 1; off < SCAN_BLK; off <<= 1) {
        int xv = (t >= off) ? sh[t - off] : 0;
        __syncthreads();
        sh[t] += xv;
        __syncthreads();
    }
    if (t < nb) g_bsum[t] = sh[t] - v;
}

// scan pass 3: apply block offsets; rowptr[N] = E
__global__ void k_scan3(int Ncur, int Ecur) {
    int idx = blockIdx.x * blockDim.x + threadIdx.x;
    if (idx < Ncur) g_rowptr[idx] += g_bsum[idx >> 8];
    if (idx == Ncur) g_rowptr[Ncur] = Ecur;
}

__global__ void k_fill(const int* __restrict__ dst, int Ecur) {
    int e = blockIdx.x * blockDim.x + threadIdx.x;
    if (e < Ecur) {
        int d = dst[e];
        int slot = g_rowptr[d] + atomicAdd(&g_fill[d], 1);
        g_eid[slot] = e;
    }
}

// sort each bucket by edge id (determinism), emit src + norm per slot.
__global__ void k_sort(const int* __restrict__ src, int Ncur) {
    int i = blockIdx.x * blockDim.x + threadIdx.x;
    if (i >= Ncur) return;
    int lo = g_rowptr[i], hi = g_rowptr[i + 1];
    int n = hi - lo;
    float di = g_dis[i];
    if (n <= 64) {
        int buf[64];
        for (int k = 0; k < n; k++) buf[k] = g_eid[lo + k];
        for (int a = 1; a < n; a++) {
            int key = buf[a];
            int b = a - 1;
            while (b >= 0 && buf[b] > key) { buf[b + 1] = buf[b]; b--; }
            buf[b + 1] = key;
        }
        for (int k = 0; k < n; k++) {
            int s = src[buf[k]];
            g_csrc[lo + k]  = s;
            g_cnorm[lo + k] = di * g_dis[s];
        }
    } else {
        for (int a = lo + 1; a < hi; a++) {
            int key = g_eid[a];
            int b = a - 1;
            while (b >= lo && g_eid[b] > key) { g_eid[b + 1] = g_eid[b]; b--; }
            g_eid[b + 1] = key;
        }
        for (int k = lo; k < hi; k++) {
            int s = src[g_eid[k]];
            g_csrc[k]  = s;
            g_cnorm[k] = di * g_dis[s];
        }
    }
}

// A = x @ W1[:, :64].T ; B = x @ W1[:, 64:].T   (16 nodes per block)
__global__ void __launch_bounds__(128) k_ab(const float* __restrict__ x,
                                            const float* __restrict__ W1, int Ncur) {
    __shared__ float xs[16][FIN];
    int j0 = blockIdx.x * 16;
    for (int idx = threadIdx.x; idx < 16 * FIN; idx += 128) {
        int j = idx >> 6, k = idx & 63;
        xs[j][k] = (j0 + j < Ncur) ? x[(j0 + j) * FIN + k] : 0.0f;
    }
    __syncthreads();
    int o = threadIdx.x;
    float accA[16], accB[16];
#pragma unroll
    for (int j = 0; j < 16; j++) { accA[j] = 0.f; accB[j] = 0.f; }
    const float* w = W1 + o * (2 * FIN);
    for (int k = 0; k < FIN; k++) {
        float wa = w[k], wb = w[FIN + k];
#pragma unroll
        for (int j = 0; j < 16; j++) {
            float xv = xs[j][k];
            accA[j] = fmaf(wa, xv, accA[j]);
            accB[j] = fmaf(wb, xv, accB[j]);
        }
    }
    for (int j = 0; j < 16; j++) {
        if (j0 + j < Ncur) {
            g_A[(j0 + j) * HID + o] = accA[j];
            g_B[(j0 + j) * HID + o] = accB[j];
        }
    }
}

// h1 rows 0..N-1: h1[j] = A[src[j]] + B[dst[j]]
__global__ void k_h1(const int* __restrict__ src, const int* __restrict__ dst, int Ncur) {
    int t = blockIdx.x * blockDim.x + threadIdx.x;
    if (t >= Ncur * HID) return;
    int j = t >> 7, f = t & 127;
    g_h1[t] = g_A[src[j] * HID + f] + g_B[dst[j] * HID + f];
}

// agg1[i] = sum over CSR bucket i of norm * h1[src]; indices staged in smem
__global__ void __launch_bounds__(128) k_agg1() {
    __shared__ int   ssrc[128];
    __shared__ float snorm[128];
    int i = blockIdx.x, f = threadIdx.x;
    int lo = g_rowptr[i], hi = g_rowptr[i + 1];
    float acc = 0.f;
    for (int base = lo; base < hi; base += 128) {
        int m = hi - base; if (m > 128) m = 128;
        if (f < m) { ssrc[f] = g_csrc[base + f]; snorm[f] = g_cnorm[base + f]; }
        __syncthreads();
        int k = 0;
        for (; k + 4 <= m; k += 4) {
            int s0 = ssrc[k], s1 = ssrc[k + 1], s2 = ssrc[k + 2], s3 = ssrc[k + 3];
            float n0 = snorm[k], n1 = snorm[k + 1], n2 = snorm[k + 2], n3 = snorm[k + 3];
            float v0 = g_h1[s0 * HID + f], v1 = g_h1[s1 * HID + f];
            float v2 = g_h1[s2 * HID + f], v3 = g_h1[s3 * HID + f];
            acc = fmaf(n0, v0, acc); acc = fmaf(n1, v1, acc);
            acc = fmaf(n2, v2, acc); acc = fmaf(n3, v3, acc);
        }
        for (; k < m; k++) acc = fmaf(snorm[k], g_h1[ssrc[k] * HID + f], acc);
        __syncthreads();
    }
    g_agg1[i * HID + f] = acc;
}

// finalize BN over both partial regions (fixed-order reduce -> deterministic)
__global__ void k_bnred(const float* __restrict__ gamma, const float* __restrict__ beta, int Ecur) {
    int f = threadIdx.x;
    float s = 0.f, q = 0.f;
    for (int b = 0; b < STATS_BLOCKS + STATS_BLOCKS_N; b++) {
        s += g_part[(size_t)b * (2 * HID) + f];
        q += g_part[(size_t)b * (2 * HID) + HID + f];
    }
    float invE = 1.0f / (float)Ecur;
    float mu  = s * invE;
    float var = q * invE - mu * mu;
    float istd = rsqrtf(var + 1e-5f);
    float a = gamma[f] * istd;
    g_af[f] = a;
    g_cf[f] = beta[f] - mu * a;
}

// W2l = Wl @ W2 ; cvec = Wl@b2 + bl
__global__ void k_w2l(const float* __restrict__ Wl, const float* __restrict__ W2,
                      const float* __restrict__ b2, const float* __restrict__ bl) {
    int t = blockIdx.x * blockDim.x + threadIdx.x;  // 8192 threads
    int o = t >> 7, f = t & 127;
    float acc = 0.f;
#pragma unroll
    for (int m = 0; m < 64; m++) acc = fmaf(Wl[o * 64 + m], W2[m * HID + f], acc);
    g_W2l[t] = acc;
    if (t < 64) {
        float cv = 0.f;
        for (int m = 0; m < 64; m++) cv = fmaf(Wl[t * 64 + m], b2[m], cv);
        g_cvec[t] = cv + bl[t];
    }
}

// wz[j] = W2l @ relu(bn(pre_j)) for j < N. 4-row batch, f32x2 matvec.
__global__ void __launch_bounds__(128) k_z(const int* __restrict__ src,
                                           const int* __restrict__ dst,
                                           const float* __restrict__ b1, int Ncur) {
    int f = threadIdx.x;
    float bb = b1[f], af = g_af[f], cf = g_cf[f];
    int o = f & 63, h = f >> 6;
    unsigned long long wp[32];
    {
        const float2* wrow = (const float2*)(g_W2l + o * HID + h * 64);
#pragma unroll
        for (int j = 0; j < 32; j++) { float2 w = wrow[j]; wp[j] = packf2(w.x, w.y); }
    }
    __shared__ __align__(16) float rsh[4][HID];
    __shared__ float ps[4][64];
    int stride = gridDim.x * 4;
    for (int j = blockIdx.x * 4; j < Ncur; j += stride) {
        int n = Ncur - j; if (n > 4) n = 4;
        int sn[4], dn[4];
#pragma unroll
        for (int r = 0; r < 4; r++) {
            int jj = (r < n) ? (j + r) : j;
            sn[r] = src[jj]; dn[r] = dst[jj];
        }
        float vA[4], vB[4], ag[4], idg[4];
#pragma unroll
        for (int r = 0; r < 4; r++) {
            int jj = (r < n) ? (j + r) : j;
            vA[r]  = g_A[sn[r] * HID + f];
            vB[r]  = g_B[dn[r] * HID + f];
            ag[r]  = g_agg1[jj * HID + f];
            idg[r] = g_invdeg[jj];
        }
#pragma unroll
        for (int r = 0; r < 4; r++) {
            float v = idg[r] * (vA[r] + vB[r]) + ag[r] + bb;
            rsh[r][f] = fmaxf(fmaf(af, v, cf), 0.f);
        }
        __syncthreads();
        float part[4];
#pragma unroll
        for (int r = 0; r < 4; r++) {
            const ulonglong2* r2 = (const ulonglong2*)(rsh[r] + h * 64);
            unsigned long long a0 = 0ull, a1 = 0ull, a2 = 0ull, a3 = 0ull;
#pragma unroll
            for (int k = 0; k < 8; k++) {
                ulonglong2 u0 = r2[2 * k];
                ulonglong2 u1 = r2[2 * k + 1];
                a0 = fma2(wp[4 * k + 0], u0.x, a0);
                a1 = fma2(wp[4 * k + 1], u0.y, a1);
                a2 = fma2(wp[4 * k + 2], u1.x, a2);
                a3 = fma2(wp[4 * k + 3], u1.y, a3);
            }
            a0 = add2(a0, a1); a2 = add2(a2, a3); a0 = add2(a0, a2);
            part[r] = f2lo(a0) + f2hi(a0);
            if (h) ps[r][o] = part[r];
        }
        __syncthreads();
        if (!h) {
#pragma unroll
            for (int r = 0; r < 4; r++)
                if (r < n) g_wz[(j + r) * FOUT + o] = part[r] + ps[r][o];
        }
        __syncthreads();
    }
}

// wa2[i] = sum over bucket i of norm * wz[src]; indices staged in smem
__global__ void __launch_bounds__(64) k_agg2() {
    __shared__ int   ssrc[64];
    __shared__ float snorm[64];
    int i = blockIdx.x, f = threadIdx.x;
    int lo = g_rowptr[i], hi = g_rowptr[i + 1];
    float acc = 0.f;
    for (int base = lo; base < hi; base += 64) {
        int m = hi - base; if (m > 64) m = 64;
        if (f < m) { ssrc[f] = g_csrc[base + f]; snorm[f] = g_cnorm[base + f]; }
        __syncthreads();
        int k = 0;
        for (; k + 4 <= m; k += 4) {
            int s0 = ssrc[k], s1 = ssrc[k + 1], s2 = ssrc[k + 2], s3 = ssrc[k + 3];
            float n0 = snorm[k], n1 = snorm[k + 1], n2 = snorm[k + 2], n3 = snorm[k + 3];
            float v0 = g_wz[s0 * FOUT + f], v1 = g_wz[s1 * FOUT + f];
            float v2 = g_wz[s2 * FOUT + f], v3 = g_wz[s3 * FOUT + f];
            acc = fmaf(n0, v0, acc); acc = fmaf(n1, v1, acc);
            acc = fmaf(n2, v2, acc); acc = fmaf(n3, v3, acc);
        }
        for (; k < m; k++) acc = fmaf(snorm[k], g_wz[ssrc[k] * FOUT + f], acc);
        __syncthreads();
    }
    g_wa2[i * FOUT + f] = acc;
}

// rows i < N: y = invdeg*wz + wa2 + cvec  (pure elementwise)
__global__ void k_small(const float* __restrict__ cutp, float* __restrict__ outp,
                        float* __restrict__ outr, int Ncur) {
    int t = blockIdx.x * blockDim.x + threadIdx.x;
    if (t >= Ncur * FOUT) return;
    int i = t >> 6, o = t & 63;
    float y = g_invdeg[i] * g_wz[t] + g_wa2[t] + g_cvec[o];
    float p = 1.0f / (1.0f + expf(-y));
    outp[t] = p;
    outr[t] = (p < *cutp) ? 0.0f : 1.0f;
}

// rows i in [N, E): 8-row batch, f32x2 matvec. 16 gathers in flight,
// 3 barriers per 8 rows (row-batching lever, third application).
__global__ void __launch_bounds__(128) k_final(const int* __restrict__ src,
                                               const int* __restrict__ dst,
                                               const float* __restrict__ b1,
                                               const float* __restrict__ cutp,
                                               float* __restrict__ outp,
                                               float* __restrict__ outr,
                                               int Ncur, int Ecur) {
    int f = threadIdx.x;
    float bb = b1[f], af = g_af[f], cf = g_cf[f];
    int o = f & 63, h = f >> 6;
    unsigned long long wp[32];
    {
        const float2* wrow = (const float2*)(g_W2l + o * HID + h * 64);
#pragma unroll
        for (int j = 0; j < 32; j++) { float2 w = wrow[j]; wp[j] = packf2(w.x, w.y); }
    }
    float cv  = g_cvec[o];
    float cut = *cutp;
    __shared__ __align__(16) float rsh[8][HID];
    __shared__ float ps[8][64];

    int stride = gridDim.x * 8;
    for (int i = Ncur + blockIdx.x * 8; i < Ecur; i += stride) {
        int n = Ecur - i; if (n > 8) n = 8;
        int sn[8], dn[8];
#pragma unroll
        for (int r = 0; r < 8; r++) {
            int ii = (r < n) ? (i + r) : i;
            sn[r] = src[ii]; dn[r] = dst[ii];
        }
        float vA[8], vB[8];
#pragma unroll
        for (int r = 0; r < 8; r++) {
            vA[r] = g_A[sn[r] * HID + f];
            vB[r] = g_B[dn[r] * HID + f];
        }
#pragma unroll
        for (int r = 0; r < 8; r++)
            rsh[r][f] = fmaxf(fmaf(af, vA[r] + vB[r] + bb, cf), 0.f);
        __syncthreads();

        float part[8];
#pragma unroll
        for (int r = 0; r < 8; r++) {
            const ulonglong2* r2 = (const ulonglong2*)(rsh[r] + h * 64);
            unsigned long long a0 = 0ull, a1 = 0ull, a2 = 0ull, a3 = 0ull;
#pragma unroll
            for (int k = 0; k < 8; k++) {
                ulonglong2 u0 = r2[2 * k];
                ulonglong2 u1 = r2[2 * k + 1];
                a0 = fma2(wp[4 * k + 0], u0.x, a0);
                a1 = fma2(wp[4 * k + 1], u0.y, a1);
                a2 = fma2(wp[4 * k + 2], u1.x, a2);
                a3 = fma2(wp[4 * k + 3], u1.y, a3);
            }
            a0 = add2(a0, a1); a2 = add2(a2, a3); a0 = add2(a0, a2);
            part[r] = f2lo(a0) + f2hi(a0);
            if (h) ps[r][o] = part[r];
        }
        __syncthreads();
        if (!h) {
#pragma unroll
            for (int r = 0; r < 8; r++) {
                if (r < n) {
                    float y = (part[r] + ps[r][o]) + cv;
                    float p = 1.0f / (1.0f + expf(-y));
                    size_t off = (size_t)(i + r) * FOUT + o;
                    outp[off] = p;
                    outr[off] = (p < cut) ? 0.0f : 1.0f;
                }
            }
        }
        __syncthreads();
    }
}

// ---------------- launch ----------------
extern "C" void kernel_launch(void* const* d_in, const int* in_sizes, int n_in,
                              void* d_out, int out_size) {
    const float* x     = (const float*)d_in[0];
    const int*   edge  = (const int*)d_in[1];
    const float* W1    = (const float*)d_in[2];
    const float* b1    = (const float*)d_in[3];
    const float* gamma = (const float*)d_in[4];
    const float* beta  = (const float*)d_in[5];
    const float* W2    = (const float*)d_in[6];
    const float* b2    = (const float*)d_in[7];
    const float* Wl    = (const float*)d_in[8];
    const float* bl    = (const float*)d_in[9];
    const float* cut   = (const float*)d_in[10];

    int Ncur = in_sizes[0] / FIN;
    int Ecur = in_sizes[1] / 2;
    if (Ncur > NMAX || Ecur > EMAX || Ncur <= 0 || Ecur <= 0) return;

    const int* src = edge;
    const int* dst = edge + Ecur;
    float* outp = (float*)d_out;
    float* outr = outp + (size_t)out_size / 2;

    int nb = (Ncur + SCAN_BLK - 1) / SCAN_BLK;

    // k_bnstatsE at launch index 3 (ncu capture window): verify occupancy
    // prediction grid 1024->2048: dur 95.9us -> ~60-70us, occ 42% -> 75%+.
    k_ab       <<<(Ncur + 15) / 16, 128>>>(x, W1, Ncur);           // 0
    k_zero     <<<(Ncur + 255) / 256, 256>>>(Ncur);                // 1
    k_count    <<<(Ecur + 255) / 256, 256>>>(dst, Ecur);           // 2
    k_bnstatsE <<<STATS_BLOCKS, 128>>>(src, dst, b1, Ncur, Ecur);  // 3 (profiled)
    k_scan1    <<<nb, SCAN_BLK>>>(Ncur);                           // 4
    k_scan2    <<<1, SCAN_BLK>>>(nb);                              // 5
    k_scan3    <<<(Ncur + 256) / 256, 256>>>(Ncur, Ecur);          // 6
    k_fill     <<<(Ecur + 255) / 256, 256>>>(dst, Ecur);           // 7
    k_sort     <<<(Ncur + 127) / 128, 128>>>(src, Ncur);           // 8
    k_h1       <<<(Ncur * HID + 255) / 256, 256>>>(src, dst, Ncur);// 9
    k_agg1     <<<Ncur, 128>>>();                                  // 10
    k_bnstatsN <<<STATS_BLOCKS_N, 128>>>(src, dst, b1, Ncur);      // 11
    k_bnred    <<<1, 128>>>(gamma, beta, Ecur);                    // 12
    k_w2l      <<<64, 128>>>(Wl, W2, b2, bl);                      // 13
    {
        int groups = (Ncur + 3) / 4;
        int g = groups < 2048 ? groups : 2048;
        k_z<<<g, 128>>>(src, dst, b1, Ncur);                       // 14
    }
    k_agg2     <<<Ncur, 64>>>();                                   // 15
    k_small    <<<(Ncur * FOUT + 255) / 256, 256>>>(cut, outp, outr, Ncur); // 16
    {
        int rows = Ecur - Ncur;
        if (rows > 0) {
            int groups = (rows + 7) / 8;
            int g = groups < 4096 ? groups : 4096;
            k_final<<<g, 128>>>(src, dst, b1, cut, outp, outr, Ncur, Ecur); // 17
        }
    }
}